// round 5
// baseline (speedup 1.0000x reference)
#include <cuda_runtime.h>

#define BSEQ 512
#define LSEQ 512
#define AA   20
#define CCH  8
#define NREST 8
#define XPITCH 258   // x_shT row pitch (words): even (float2 align), ==2 mod 32

// Precomputed: effective conv map (transposed, [c][p]) and U = I + V
__device__ float g_W[CCH][LSEQ];
__device__ float g_U[AA * AA];

// ---------------------------------------------------------------------------
// Precompute kernel: blocks 0..7 -> one channel of W_eff (adjoint of the
// conv+pool pipeline); block 8 -> U; blocks 9..168 -> zero d_out.
// Small layers (len2<=32) run warp-synchronously in warp 0.
// ---------------------------------------------------------------------------
template<int LEN2, bool WARP0>
__device__ __forceinline__ void adj_layer(const float (*cur)[256],
                                          float (*nxt)[256],
                                          const float* __restrict__ w) {
    const int step = WARP0 ? 32 : 256;
    const int t0   = WARP0 ? (threadIdx.x & 31) : threadIdx.x;
    for (int idx = t0; idx < CCH * LEN2; idx += step) {
        const int i = idx / LEN2;
        const int p = idx % LEN2;
        float acc = 0.f;
        #pragma unroll
        for (int o = 0; o < CCH; ++o) {
            #pragma unroll
            for (int k = 0; k < 3; ++k) {
                const int q = p - k + 1;
                if (q >= 0 && q < LEN2)
                    acc += w[(o * CCH + i) * 3 + k] * 0.5f * cur[o][q >> 1];
            }
        }
        nxt[i][p] = acc;
    }
    if (WARP0) __syncwarp();
    else       __syncthreads();
}

__global__ void __launch_bounds__(256)
precompute_kernel(const float* __restrict__ lpm,
                  const float* __restrict__ pm,
                  const float* __restrict__ w_first,
                  const float* __restrict__ w_rest,
                  float* __restrict__ out) {
    const int blk = blockIdx.x;
    const int tid = threadIdx.x;

    if (blk < CCH) {
        __shared__ float bufA[CCH][256];
        __shared__ float bufB[CCH][256];
        __shared__ float wsh[NREST * CCH * CCH * 3];

        for (int i = tid; i < NREST * CCH * CCH * 3; i += blockDim.x)
            wsh[i] = w_rest[i];
        if (tid < CCH) bufA[tid][0] = (tid == blk) ? 1.f : 0.f;
        __syncthreads();

        float (*cur)[256] = bufA;
        float (*nxt)[256] = bufB;
        float (*tmp)[256];
        #define STEPW(L2, LI) \
            if (tid < 32) adj_layer<L2, true>(cur, nxt, wsh + (LI) * 192); \
            tmp = cur; cur = nxt; nxt = tmp;
        #define STEPB(L2, LI) \
            adj_layer<L2, false>(cur, nxt, wsh + (LI) * 192); \
            tmp = cur; cur = nxt; nxt = tmp;
        STEPW(2, 7)  STEPW(4, 6)  STEPW(8, 5)  STEPW(16, 4)  STEPW(32, 3)
        __syncthreads();
        STEPB(64, 2) STEPB(128, 1) STEPB(256, 0)
        #undef STEPW
        #undef STEPB

        for (int p = tid; p < LSEQ; p += blockDim.x) {
            float acc = 0.f;
            #pragma unroll
            for (int o = 0; o < CCH; ++o) {
                #pragma unroll
                for (int k = 0; k < 3; ++k) {
                    const int q = p - k + 1;
                    if (q >= 0 && q < LSEQ)
                        acc += w_first[o * 3 + k] * 0.5f * cur[o][q >> 1];
                }
            }
            g_W[blk][p] = acc;            // transposed layout [c][p]
        }
    } else if (blk == CCH) {
        // U[a][i] = delta(a,i) + V[a][i]
        for (int idx = tid; idx < AA * AA; idx += blockDim.x) {
            const int a = idx / AA, i = idx % AA;
            float v = (a == i) ? 1.f : 0.f;
            if (i != a && i != AA - 1) {
                const int r = (a < i) ? a : i;
                const int c = (a < i) ? i : a;
                float l = lpm[r * AA + c];
                l = fminf(fmaxf(l, 1e-3f), 1.f);
                v = l * pm[r * AA + c];
            }
            g_U[idx] = v;
        }
    } else {
        const int z = blk - (CCH + 1);          // 0..159
        if (tid < 128)
            reinterpret_cast<float4*>(out)[z * 128 + tid] =
                make_float4(0.f, 0.f, 0.f, 0.f);
    }
}

// ---------------------------------------------------------------------------
// Main kernel: grid 1024 = 512 sequences x 2 halves of 256 positions.
// x stored TRANSPOSED in shared ([a][p], pitch 258) so the GEMM loop reads
// both x and W as conflict-free LDS.64 over consecutive p. 8 warps = 4
// a-groups x 2 c-halves; warp tile 5a x 4c, K=256.
// ---------------------------------------------------------------------------
__global__ void __launch_bounds__(256, 6)
main_kernel(const float* __restrict__ x, float* __restrict__ out) {
    __shared__ float x_shT[AA * XPITCH];    // 20640 B
    __shared__ float W_sh[CCH * 256];       //  8192 B
    __shared__ float g_sh[AA][CCH];         //   640 B

    const int bi   = blockIdx.x;
    const int b    = bi >> 1;
    const int half = bi & 1;
    const int tid  = threadIdx.x;
    const int s    = tid & 31;
    const int w    = tid >> 5;
    const int gq   = w >> 1;                // a-group 0..3 (rows 5gq..5gq+4)
    const int h    = w & 1;                 // c-half 0..1 (cols 4h..4h+3)

    // Stage W chunk [8][256].
    {
        const float4* Wg = reinterpret_cast<const float4*>(g_W);
        #pragma unroll
        for (int it = 0; it < 2; ++it) {
            const int i = tid + it * 256;    // < 512
            const int c = i >> 6, p4 = i & 63;
            reinterpret_cast<float4*>(W_sh)[c * 64 + p4] =
                Wg[c * 128 + half * 64 + p4];
        }
    }

    // Stage x half-chunk: coalesced float4 global loads, transposed scatter.
    // Store banks: word addr = 258*a + p == (2a + p) mod 32 -> <=2-way.
    {
        const float4* xg = reinterpret_cast<const float4*>(x)
                         + (size_t)b * 2560 + half * 1280;
        #pragma unroll
        for (int it = 0; it < 5; ++it) {
            const int i = tid + it * 256;    // < 1280
            const float4 v = xg[i];
            const int p  = i / 5;
            const int a0 = (i - p * 5) * 4;
            x_shT[(a0 + 0) * XPITCH + p] = v.x;
            x_shT[(a0 + 1) * XPITCH + p] = v.y;
            x_shT[(a0 + 2) * XPITCH + p] = v.z;
            x_shT[(a0 + 3) * XPITCH + p] = v.w;
        }
    }
    __syncthreads();

    float acc[5][4];
    #pragma unroll
    for (int m = 0; m < 5; ++m)
        #pragma unroll
        for (int n = 0; n < 4; ++n) acc[m][n] = 0.f;

    // Lane s covers p in {64j + 2s, 64j + 2s + 1}, j = 0..3. All LDS.64,
    // conflict-free (consecutive lanes -> consecutive word pairs).
    const float2* xp = reinterpret_cast<const float2*>(
        &x_shT[(gq * 5) * XPITCH + 2 * s]);
    const float2* wp = reinterpret_cast<const float2*>(
        &W_sh[(h * 4) * 256 + 2 * s]);
    #pragma unroll
    for (int j = 0; j < 4; ++j) {
        float2 wr[4];
        #pragma unroll
        for (int n = 0; n < 4; ++n) wr[n] = wp[n * 128 + j * 32];
        #pragma unroll
        for (int m = 0; m < 5; ++m) {
            const float2 xr = xp[m * (XPITCH / 2) + j * 32];
            #pragma unroll
            for (int n = 0; n < 4; ++n) {
                acc[m][n] += xr.x * wr[n].x;
                acc[m][n] += xr.y * wr[n].y;
            }
        }
    }

    // Value-combining butterfly reduce over lanes.
    const bool hi16 = (s & 16) != 0;
    const bool hi8  = (s & 8) != 0;
    float r1[5][2];
    #pragma unroll
    for (int m = 0; m < 5; ++m) {
        #pragma unroll
        for (int u = 0; u < 2; ++u) {
            const float a = acc[m][2 * u];
            const float bb = acc[m][2 * u + 1];
            const float keep = hi16 ? bb : a;
            const float send = hi16 ? a : bb;
            r1[m][u] = keep + __shfl_xor_sync(0xffffffffu, send, 16);
        }
    }
    float r2[5];
    #pragma unroll
    for (int m = 0; m < 5; ++m) {
        const float a = r1[m][0];
        const float bb = r1[m][1];
        const float keep = hi8 ? bb : a;
        const float send = hi8 ? a : bb;
        r2[m] = keep + __shfl_xor_sync(0xffffffffu, send, 8);
    }
    #pragma unroll
    for (int m = 0; m < 5; ++m) {
        r2[m] += __shfl_xor_sync(0xffffffffu, r2[m], 4);
        r2[m] += __shfl_xor_sync(0xffffffffu, r2[m], 2);
        r2[m] += __shfl_xor_sync(0xffffffffu, r2[m], 1);
    }
    if ((s & 7) == 0) {
        const int n = 2 * ((s >> 3) & 1) + ((s >> 4) & 1);
        #pragma unroll
        for (int m = 0; m < 5; ++m)
            g_sh[gq * 5 + m][h * 4 + n] = r2[m];
    }
    __syncthreads();

    // out[b,i,c] += sum_a U[a][i] * g[a][c]   (2 halves combine via atomics)
    if (tid < AA * CCH) {
        const int i = tid >> 3;
        const int c = tid & 7;
        float r = 0.f;
        #pragma unroll
        for (int a = 0; a < AA; ++a)
            r += __ldg(&g_U[a * AA + i]) * g_sh[a][c];
        atomicAdd(&out[(size_t)b * (AA * CCH) + tid], r);
    }
}

// ---------------------------------------------------------------------------
extern "C" void kernel_launch(void* const* d_in, const int* in_sizes, int n_in,
                              void* d_out, int out_size) {
    const float* x       = (const float*)d_in[0];
    const float* lpm     = (const float*)d_in[2];
    const float* pm      = (const float*)d_in[3];
    const float* w_first = (const float*)d_in[4];
    const float* w_rest  = (const float*)d_in[5];
    float* out = (float*)d_out;

    precompute_kernel<<<CCH + 1 + 160, 256>>>(lpm, pm, w_first, w_rest, out);
    main_kernel<<<BSEQ * 2, 256>>>(x, out);
}

// round 6
// speedup vs baseline: 1.0076x; 1.0076x over previous
#include <cuda_runtime.h>

#define BSEQ 512
#define LSEQ 512
#define AA   20
#define CCH  8
#define NREST 8
#define XPAD 21              // x_sh row pitch: gcd(21,32)=1 -> conflict-free
#define GRID (BSEQ * 2)
#define NPRE 9u

// Precomputed: effective conv map (transposed, [c][p]) and U = I + V
__device__ float    g_W[CCH][LSEQ];
__device__ float    g_U[AA * AA];
__device__ unsigned g_flag = 0;      // counts publishers (ready when == NPRE)
__device__ unsigned g_done = 0;      // end-of-launch reset coordination

struct PreShared {                    // 22528 B
    float bufA[CCH][256];
    float bufB[CCH][256];
    float wsh[NREST * CCH * CCH * 3];
};
struct GemmShared {                   // 29696 B
    float x_sh[256 * XPAD];
    float W_sh[CCH * 256];
};
#define SRAW_BYTES (sizeof(GemmShared) > sizeof(PreShared) ? \
                    sizeof(GemmShared) : sizeof(PreShared))

// Adjoint of one conv(3,pad1)+avgpool(2) layer, block-cooperative.
template<int LEN2>
__device__ __forceinline__ void adj_layer(const float (*cur)[256],
                                          float (*nxt)[256],
                                          const float* __restrict__ w) {
    for (int idx = threadIdx.x; idx < CCH * LEN2; idx += 256) {
        const int i = idx / LEN2;
        const int p = idx % LEN2;
        float acc = 0.f;
        #pragma unroll
        for (int o = 0; o < CCH; ++o) {
            #pragma unroll
            for (int k = 0; k < 3; ++k) {
                const int q = p - k + 1;
                if (q >= 0 && q < LEN2)
                    acc += w[(o * CCH + i) * 3 + k] * 0.5f * cur[o][q >> 1];
            }
        }
        nxt[i][p] = acc;
    }
    __syncthreads();
}

// ---------------------------------------------------------------------------
// Single fused kernel. Blocks 0..8 first build W_eff/U and zero `out`, then
// publish via g_flag. Every block stages its x chunk (overlapping the
// precompute phase), waits for readiness, and runs the R4 GEMM + epilogue.
// ---------------------------------------------------------------------------
__global__ void __launch_bounds__(256, 7)
fused_kernel(const float* __restrict__ x,
             const float* __restrict__ lpm,
             const float* __restrict__ pm,
             const float* __restrict__ w_first,
             const float* __restrict__ w_rest,
             float* __restrict__ out) {
    __shared__ __align__(16) char sraw[SRAW_BYTES];
    __shared__ float g_sh[AA][CCH];

    const int bi   = blockIdx.x;
    const int tid  = threadIdx.x;

    // ---------------- Phase 0: precompute (blocks 0..8 only) ----------------
    if (bi < (int)NPRE) {
        if (bi < CCH) {
            PreShared& ps = *reinterpret_cast<PreShared*>(sraw);
            for (int i = tid; i < NREST * CCH * CCH * 3; i += 256)
                ps.wsh[i] = w_rest[i];
            if (tid < CCH) ps.bufA[tid][0] = (tid == bi) ? 1.f : 0.f;
            __syncthreads();

            float (*cur)[256] = ps.bufA;
            float (*nxt)[256] = ps.bufB;
            float (*tmp)[256];
            #define STEP(L2, LI) \
                adj_layer<L2>(cur, nxt, ps.wsh + (LI) * 192); \
                tmp = cur; cur = nxt; nxt = tmp;
            STEP(2, 7)  STEP(4, 6)  STEP(8, 5)   STEP(16, 4)
            STEP(32, 3) STEP(64, 2) STEP(128, 1) STEP(256, 0)
            #undef STEP

            for (int p = tid; p < LSEQ; p += 256) {
                float acc = 0.f;
                #pragma unroll
                for (int o = 0; o < CCH; ++o) {
                    #pragma unroll
                    for (int k = 0; k < 3; ++k) {
                        const int q = p - k + 1;
                        if (q >= 0 && q < LSEQ)
                            acc += w_first[o * 3 + k] * 0.5f * cur[o][q >> 1];
                    }
                }
                g_W[bi][p] = acc;        // transposed layout [c][p]
            }
        } else {
            // U[a][i] = delta(a,i) + V[a][i]
            for (int idx = tid; idx < AA * AA; idx += 256) {
                const int a = idx / AA, i = idx % AA;
                float v = (a == i) ? 1.f : 0.f;
                if (i != a && i != AA - 1) {
                    const int r = (a < i) ? a : i;
                    const int c = (a < i) ? i : a;
                    float l = lpm[r * AA + c];
                    l = fminf(fmaxf(l, 1e-3f), 1.f);
                    v = l * pm[r * AA + c];
                }
                g_U[idx] = v;
            }
        }
        // Zero out slice (out = 512*160 floats = 20480 float4, split 9 ways).
        {
            float4* o4 = reinterpret_cast<float4*>(out);
            const int lo = bi * 2276;
            const int hi = (lo + 2276 < 20480) ? lo + 2276 : 20480;
            for (int i = lo + tid; i < hi; i += 256)
                o4[i] = make_float4(0.f, 0.f, 0.f, 0.f);
        }
        __threadfence();
        __syncthreads();
        if (tid == 0) atomicAdd(&g_flag, 1u);
    }

    // ---------------- Phase 1: stage x (all blocks; overlaps precompute) ----
    GemmShared& gs = *reinterpret_cast<GemmShared*>(sraw);
    const int b    = bi >> 1;
    const int half = bi & 1;
    const int s    = tid & 31;
    const int w    = tid >> 5;
    const int gq   = w >> 1;                 // a-group 0..3
    const int h    = w & 1;                  // c-half 0..1

    {
        const float4* xg = reinterpret_cast<const float4*>(x)
                         + (size_t)b * 2560 + half * 1280;
        #pragma unroll
        for (int it = 0; it < 5; ++it) {
            const int i = tid + it * 256;    // < 1280
            const float4 v = xg[i];
            const int p  = i / 5;
            const int a0 = (i - p * 5) * 4;
            float* d = &gs.x_sh[p * XPAD + a0];
            d[0] = v.x; d[1] = v.y; d[2] = v.z; d[3] = v.w;
        }
    }

    // ---------------- Phase 2: wait for W/U readiness ------------------------
    if (tid == 0) {
        volatile unsigned* f = &g_flag;
        while (*f != NPRE) __nanosleep(256);
        __threadfence();
    }
    __syncthreads();

    // Stage W chunk [8][256].
    {
        const float4* Wg = reinterpret_cast<const float4*>(g_W);
        #pragma unroll
        for (int it = 0; it < 2; ++it) {
            const int i = tid + it * 256;    // < 512
            const int c = i >> 6, p4 = i & 63;
            reinterpret_cast<float4*>(gs.W_sh)[c * 64 + p4] =
                Wg[c * 128 + half * 64 + p4];
        }
    }
    __syncthreads();

    // ---------------- Phase 3: GEMM (R4 body) -------------------------------
    float acc[5][4];
    #pragma unroll
    for (int m = 0; m < 5; ++m)
        #pragma unroll
        for (int n = 0; n < 4; ++n) acc[m][n] = 0.f;

    const float* xp = &gs.x_sh[s * XPAD + gq * 5];
    const float* wp = &gs.W_sh[(h * 4) * 256 + s];
    #pragma unroll
    for (int j = 0; j < 8; ++j) {            // p = 32*j + s
        float xr[5], wr[4];
        #pragma unroll
        for (int m = 0; m < 5; ++m) xr[m] = xp[j * 32 * XPAD + m];
        #pragma unroll
        for (int n = 0; n < 4; ++n) wr[n] = wp[n * 256 + j * 32];
        #pragma unroll
        for (int m = 0; m < 5; ++m)
            #pragma unroll
            for (int n = 0; n < 4; ++n)
                acc[m][n] += xr[m] * wr[n];
    }

    // Value-combining butterfly reduce over lanes.
    const bool hi16 = (s & 16) != 0;
    const bool hi8  = (s & 8) != 0;
    float r1[5][2];
    #pragma unroll
    for (int m = 0; m < 5; ++m) {
        #pragma unroll
        for (int u = 0; u < 2; ++u) {
            const float a  = acc[m][2 * u];
            const float bb = acc[m][2 * u + 1];
            const float keep = hi16 ? bb : a;
            const float send = hi16 ? a : bb;
            r1[m][u] = keep + __shfl_xor_sync(0xffffffffu, send, 16);
        }
    }
    float r2[5];
    #pragma unroll
    for (int m = 0; m < 5; ++m) {
        const float a  = r1[m][0];
        const float bb = r1[m][1];
        const float keep = hi8 ? bb : a;
        const float send = hi8 ? a : bb;
        r2[m] = keep + __shfl_xor_sync(0xffffffffu, send, 8);
    }
    #pragma unroll
    for (int m = 0; m < 5; ++m) {
        r2[m] += __shfl_xor_sync(0xffffffffu, r2[m], 4);
        r2[m] += __shfl_xor_sync(0xffffffffu, r2[m], 2);
        r2[m] += __shfl_xor_sync(0xffffffffu, r2[m], 1);
    }
    if ((s & 7) == 0) {
        const int n = 2 * ((s >> 3) & 1) + ((s >> 4) & 1);
        #pragma unroll
        for (int m = 0; m < 5; ++m)
            g_sh[gq * 5 + m][h * 4 + n] = r2[m];
    }
    __syncthreads();

    // out[b,i,c] += sum_a U[a][i] * g[a][c]   (2 halves combine via atomics)
    if (tid < AA * CCH) {
        const int i = tid >> 3;
        const int c = tid & 7;
        float r = 0.f;
        #pragma unroll
        for (int a = 0; a < AA; ++a)
            r += __ldg(&g_U[a * AA + i]) * g_sh[a][c];
        atomicAdd(&out[(size_t)b * (AA * CCH) + tid], r);
    }

    // ---------------- Phase 4: reset flags for the next launch --------------
    if (tid == 0) {
        const unsigned d = atomicAdd(&g_done, 1u);
        if (d == (unsigned)(GRID - 1)) {   // last block: everyone passed wait
            g_done = 0u;
            g_flag = 0u;
            __threadfence();
        }
    }
}

// ---------------------------------------------------------------------------
extern "C" void kernel_launch(void* const* d_in, const int* in_sizes, int n_in,
                              void* d_out, int out_size) {
    const float* x       = (const float*)d_in[0];
    const float* lpm     = (const float*)d_in[2];
    const float* pm      = (const float*)d_in[3];
    const float* w_first = (const float*)d_in[4];
    const float* w_rest  = (const float*)d_in[5];
    float* out = (float*)d_out;

    fused_kernel<<<GRID, 256>>>(x, lpm, pm, w_first, w_rest, out);
}

// round 7
// speedup vs baseline: 1.0107x; 1.0030x over previous
#include <cuda_runtime.h>

#define BSEQ 512
#define LSEQ 512
#define AA   20
#define CCH  8
#define NREST 8
#define XPAD 21              // x_sh row pitch: gcd(21,32)=1 -> conflict-free
#define GRID (BSEQ * 2)
#define NPRE 9u

// Precomputed: effective conv map (transposed, [c][p]) and U = I + V
__device__ float    g_W[CCH][LSEQ];
__device__ float    g_U[AA * AA];
__device__ unsigned g_flag = 0;      // counts publishers (ready when == NPRE)
__device__ unsigned g_done = 0;      // end-of-launch reset coordination

struct PreShared {                    // 22528 B
    float bufA[CCH][256];
    float bufB[CCH][256];
    float wsh[NREST * CCH * CCH * 3];
};
struct GemmShared {                   // 29696 B
    float x_sh[256 * XPAD];
    float W_sh[CCH * 256];
};
#define SRAW_BYTES (sizeof(GemmShared) > sizeof(PreShared) ? \
                    sizeof(GemmShared) : sizeof(PreShared))

// Adjoint of one conv(3,pad1)+avgpool(2) layer, block-cooperative.
template<int LEN2>
__device__ __forceinline__ void adj_layer(const float (*cur)[256],
                                          float (*nxt)[256],
                                          const float* __restrict__ w) {
    for (int idx = threadIdx.x; idx < CCH * LEN2; idx += 256) {
        const int i = idx / LEN2;
        const int p = idx % LEN2;
        float acc = 0.f;
        #pragma unroll
        for (int o = 0; o < CCH; ++o) {
            #pragma unroll
            for (int k = 0; k < 3; ++k) {
                const int q = p - k + 1;
                if (q >= 0 && q < LEN2)
                    acc += w[(o * CCH + i) * 3 + k] * 0.5f * cur[o][q >> 1];
            }
        }
        nxt[i][p] = acc;
    }
    __syncthreads();
}

// ---------------------------------------------------------------------------
// Single fused kernel.
//   Phase -1 (all blocks): prefetch this block's x chunk into L2.
//   Phase 0 (blocks 0..8): build W_eff / U, zero out, publish g_flag.
//   Phase 1 (all blocks): wait for flag, THEN stage W + x and run the R4
//   GEMM body — identical per-block pipeline to the proven 11.7us kernel,
//   but with x already resident in L2.
// ---------------------------------------------------------------------------
__global__ void __launch_bounds__(256, 7)
fused_kernel(const float* __restrict__ x,
             const float* __restrict__ lpm,
             const float* __restrict__ pm,
             const float* __restrict__ w_first,
             const float* __restrict__ w_rest,
             float* __restrict__ out) {
    __shared__ __align__(16) char sraw[SRAW_BYTES];
    __shared__ float g_sh[AA][CCH];

    const int bi   = blockIdx.x;
    const int tid  = threadIdx.x;
    const int b    = bi >> 1;
    const int half = bi & 1;

    // ---------------- Phase -1: L2 prefetch of this block's x chunk ---------
    // Chunk = 1280 float4 = 20480 B = 160 cache lines.
    if (tid < 160) {
        const char* pc = reinterpret_cast<const char*>(x)
                       + ((size_t)b * 2560 + half * 1280) * 16
                       + (size_t)tid * 128;
        asm volatile("prefetch.global.L2 [%0];" :: "l"(pc));
    }

    // ---------------- Phase 0: precompute (blocks 0..8 only) ----------------
    if (bi < (int)NPRE) {
        if (bi < CCH) {
            PreShared& ps = *reinterpret_cast<PreShared*>(sraw);
            for (int i = tid; i < NREST * CCH * CCH * 3; i += 256)
                ps.wsh[i] = w_rest[i];
            if (tid < CCH) ps.bufA[tid][0] = (tid == bi) ? 1.f : 0.f;
            __syncthreads();

            float (*cur)[256] = ps.bufA;
            float (*nxt)[256] = ps.bufB;
            float (*tmp)[256];
            #define STEP(L2, LI) \
                adj_layer<L2>(cur, nxt, ps.wsh + (LI) * 192); \
                tmp = cur; cur = nxt; nxt = tmp;
            STEP(2, 7)  STEP(4, 6)  STEP(8, 5)   STEP(16, 4)
            STEP(32, 3) STEP(64, 2) STEP(128, 1) STEP(256, 0)
            #undef STEP

            for (int p = tid; p < LSEQ; p += 256) {
                float acc = 0.f;
                #pragma unroll
                for (int o = 0; o < CCH; ++o) {
                    #pragma unroll
                    for (int k = 0; k < 3; ++k) {
                        const int q = p - k + 1;
                        if (q >= 0 && q < LSEQ)
                            acc += w_first[o * 3 + k] * 0.5f * cur[o][q >> 1];
                    }
                }
                g_W[bi][p] = acc;        // transposed layout [c][p]
            }
        } else {
            // U[a][i] = delta(a,i) + V[a][i]
            for (int idx = tid; idx < AA * AA; idx += 256) {
                const int a = idx / AA, i = idx % AA;
                float v = (a == i) ? 1.f : 0.f;
                if (i != a && i != AA - 1) {
                    const int r = (a < i) ? a : i;
                    const int c = (a < i) ? i : a;
                    float l = lpm[r * AA + c];
                    l = fminf(fmaxf(l, 1e-3f), 1.f);
                    v = l * pm[r * AA + c];
                }
                g_U[idx] = v;
            }
        }
        // Zero out slice (out = 20480 float4, split across the 9 blocks).
        {
            float4* o4 = reinterpret_cast<float4*>(out);
            const int lo = bi * 2276;
            const int hi = (lo + 2276 < 20480) ? lo + 2276 : 20480;
            for (int i = lo + tid; i < hi; i += 256)
                o4[i] = make_float4(0.f, 0.f, 0.f, 0.f);
        }
        __threadfence();
        __syncthreads();
        if (tid == 0) atomicAdd(&g_flag, 1u);
    }

    // ---------------- Phase 1: wait for W/U readiness ------------------------
    if (tid == 0) {
        volatile unsigned* f = &g_flag;
        while (*f != NPRE) __nanosleep(64);
        __threadfence();
    }
    __syncthreads();

    // ---------------- Phase 2: stage W + x (R4 pipeline, x now in L2) -------
    GemmShared& gs = *reinterpret_cast<GemmShared*>(sraw);
    const int s  = tid & 31;
    const int w  = tid >> 5;
    const int gq = w >> 1;                   // a-group 0..3
    const int h  = w & 1;                    // c-half 0..1

    {
        const float4* Wg = reinterpret_cast<const float4*>(g_W);
        #pragma unroll
        for (int it = 0; it < 2; ++it) {
            const int i = tid + it * 256;    // < 512
            const int c = i >> 6, p4 = i & 63;
            reinterpret_cast<float4*>(gs.W_sh)[c * 64 + p4] =
                Wg[c * 128 + half * 64 + p4];
        }
    }
    {
        const float4* xg = reinterpret_cast<const float4*>(x)
                         + (size_t)b * 2560 + half * 1280;
        #pragma unroll
        for (int it = 0; it < 5; ++it) {
            const int i = tid + it * 256;    // < 1280
            const float4 v = xg[i];
            const int p  = i / 5;
            const int a0 = (i - p * 5) * 4;
            float* d = &gs.x_sh[p * XPAD + a0];
            d[0] = v.x; d[1] = v.y; d[2] = v.z; d[3] = v.w;
        }
    }
    __syncthreads();

    // ---------------- Phase 3: GEMM (R4 body) -------------------------------
    float acc[5][4];
    #pragma unroll
    for (int m = 0; m < 5; ++m)
        #pragma unroll
        for (int n = 0; n < 4; ++n) acc[m][n] = 0.f;

    const float* xp = &gs.x_sh[s * XPAD + gq * 5];
    const float* wp = &gs.W_sh[(h * 4) * 256 + s];
    #pragma unroll
    for (int j = 0; j < 8; ++j) {            // p = 32*j + s
        float xr[5], wr[4];
        #pragma unroll
        for (int m = 0; m < 5; ++m) xr[m] = xp[j * 32 * XPAD + m];
        #pragma unroll
        for (int n = 0; n < 4; ++n) wr[n] = wp[n * 256 + j * 32];
        #pragma unroll
        for (int m = 0; m < 5; ++m)
            #pragma unroll
            for (int n = 0; n < 4; ++n)
                acc[m][n] += xr[m] * wr[n];
    }

    // Value-combining butterfly reduce over lanes.
    const bool hi16 = (s & 16) != 0;
    const bool hi8  = (s & 8) != 0;
    float r1[5][2];
    #pragma unroll
    for (int m = 0; m < 5; ++m) {
        #pragma unroll
        for (int u = 0; u < 2; ++u) {
            const float a  = acc[m][2 * u];
            const float bb = acc[m][2 * u + 1];
            const float keep = hi16 ? bb : a;
            const float send = hi16 ? a : bb;
            r1[m][u] = keep + __shfl_xor_sync(0xffffffffu, send, 16);
        }
    }
    float r2[5];
    #pragma unroll
    for (int m = 0; m < 5; ++m) {
        const float a  = r1[m][0];
        const float bb = r1[m][1];
        const float keep = hi8 ? bb : a;
        const float send = hi8 ? a : bb;
        r2[m] = keep + __shfl_xor_sync(0xffffffffu, send, 8);
    }
    #pragma unroll
    for (int m = 0; m < 5; ++m) {
        r2[m] += __shfl_xor_sync(0xffffffffu, r2[m], 4);
        r2[m] += __shfl_xor_sync(0xffffffffu, r2[m], 2);
        r2[m] += __shfl_xor_sync(0xffffffffu, r2[m], 1);
    }
    if ((s & 7) == 0) {
        const int n = 2 * ((s >> 3) & 1) + ((s >> 4) & 1);
        #pragma unroll
        for (int m = 0; m < 5; ++m)
            g_sh[gq * 5 + m][h * 4 + n] = r2[m];
    }
    __syncthreads();

    // out[b,i,c] += sum_a U[a][i] * g[a][c]   (2 halves combine via atomics)
    if (tid < AA * CCH) {
        const int i = tid >> 3;
        const int c = tid & 7;
        float r = 0.f;
        #pragma unroll
        for (int a = 0; a < AA; ++a)
            r += __ldg(&g_U[a * AA + i]) * g_sh[a][c];
        atomicAdd(&out[(size_t)b * (AA * CCH) + tid], r);
    }

    // ---------------- Phase 4: reset flags for the next launch --------------
    if (tid == 0) {
        const unsigned d = atomicAdd(&g_done, 1u);
        if (d == (unsigned)(GRID - 1)) {   // last block: everyone passed wait
            g_done = 0u;
            g_flag = 0u;
            __threadfence();
        }
    }
}

// ---------------------------------------------------------------------------
extern "C" void kernel_launch(void* const* d_in, const int* in_sizes, int n_in,
                              void* d_out, int out_size) {
    const float* x       = (const float*)d_in[0];
    const float* lpm     = (const float*)d_in[2];
    const float* pm      = (const float*)d_in[3];
    const float* w_first = (const float*)d_in[4];
    const float* w_rest  = (const float*)d_in[5];
    float* out = (float*)d_out;

    fused_kernel<<<GRID, 256>>>(x, lpm, pm, w_first, w_rest, out);
}

// round 8
// speedup vs baseline: 1.1218x; 1.1100x over previous
#include <cuda_runtime.h>

#define BSEQ 512
#define LSEQ 512
#define AA   20
#define CCH  8
#define NREST 8
#define XPITCH 258   // x_shT row pitch (words): even (LDS.64 align), ==2 mod 32

// Packed f32x2 FMA: acc += a * b, two independent fp32 lanes (sm_100+).
#define FFMA2(acc, a, b) \
    asm("fma.rn.f32x2 %0, %1, %2, %0;" : "+l"(acc) : "l"(a), "l"(b))
#define UNPACK2(lo, hi, v) \
    asm("mov.b64 {%0, %1}, %2;" : "=f"(lo), "=f"(hi) : "l"(v))

// Precomputed: effective conv map (transposed, [c][p]) and U = I + V
__device__ float g_W[CCH][LSEQ];
__device__ float g_U[AA * AA];

// ---------------------------------------------------------------------------
// Precompute kernel (R4, proven): blocks 0..7 -> one W_eff channel via the
// adjoint of the conv+pool pipeline; block 8 -> U; blocks 9..168 -> zero out.
// ---------------------------------------------------------------------------
template<int LEN2>
__device__ __forceinline__ void adj_layer(const float (*cur)[256],
                                          float (*nxt)[256],
                                          const float* __restrict__ w) {
    for (int idx = threadIdx.x; idx < CCH * LEN2; idx += 256) {
        const int i = idx / LEN2;
        const int p = idx % LEN2;
        float acc = 0.f;
        #pragma unroll
        for (int o = 0; o < CCH; ++o) {
            #pragma unroll
            for (int k = 0; k < 3; ++k) {
                const int q = p - k + 1;
                if (q >= 0 && q < LEN2)
                    acc += w[(o * CCH + i) * 3 + k] * 0.5f * cur[o][q >> 1];
            }
        }
        nxt[i][p] = acc;
    }
    __syncthreads();
}

__global__ void __launch_bounds__(256)
precompute_kernel(const float* __restrict__ lpm,
                  const float* __restrict__ pm,
                  const float* __restrict__ w_first,
                  const float* __restrict__ w_rest,
                  float* __restrict__ out) {
    const int blk = blockIdx.x;
    const int tid = threadIdx.x;

    if (blk < CCH) {
        __shared__ float bufA[CCH][256];
        __shared__ float bufB[CCH][256];
        __shared__ float wsh[NREST * CCH * CCH * 3];

        for (int i = tid; i < NREST * CCH * CCH * 3; i += 256)
            wsh[i] = w_rest[i];
        if (tid < CCH) bufA[tid][0] = (tid == blk) ? 1.f : 0.f;
        __syncthreads();

        float (*cur)[256] = bufA;
        float (*nxt)[256] = bufB;
        float (*tmp)[256];
        #define STEP(L2, LI) \
            adj_layer<L2>(cur, nxt, wsh + (LI) * 192); \
            tmp = cur; cur = nxt; nxt = tmp;
        STEP(2, 7)  STEP(4, 6)  STEP(8, 5)   STEP(16, 4)
        STEP(32, 3) STEP(64, 2) STEP(128, 1) STEP(256, 0)
        #undef STEP

        for (int p = tid; p < LSEQ; p += 256) {
            float acc = 0.f;
            #pragma unroll
            for (int o = 0; o < CCH; ++o) {
                #pragma unroll
                for (int k = 0; k < 3; ++k) {
                    const int q = p - k + 1;
                    if (q >= 0 && q < LSEQ)
                        acc += w_first[o * 3 + k] * 0.5f * cur[o][q >> 1];
                }
            }
            g_W[blk][p] = acc;            // transposed layout [c][p]
        }
    } else if (blk == CCH) {
        // U[a][i] = delta(a,i) + V[a][i]
        for (int idx = tid; idx < AA * AA; idx += 256) {
            const int a = idx / AA, i = idx % AA;
            float v = (a == i) ? 1.f : 0.f;
            if (i != a && i != AA - 1) {
                const int r = (a < i) ? a : i;
                const int c = (a < i) ? i : a;
                float l = lpm[r * AA + c];
                l = fminf(fmaxf(l, 1e-3f), 1.f);
                v = l * pm[r * AA + c];
            }
            g_U[idx] = v;
        }
    } else {
        const int z = blk - (CCH + 1);          // 0..159
        if (tid < 128)
            reinterpret_cast<float4*>(out)[z * 128 + tid] =
                make_float4(0.f, 0.f, 0.f, 0.f);
    }
}

// ---------------------------------------------------------------------------
// Main kernel: grid 1024 = 512 sequences x 2 halves of 256 positions.
// x stored TRANSPOSED ([a][p], pitch 258); GEMM loop pairs even/odd p into
// packed f32x2 accumulators fed by conflict-free LDS.64 on both operands.
// 8 warps = 4 a-groups x 2 c-halves; warp tile 5a x 4c, K=256.
// ---------------------------------------------------------------------------
__global__ void __launch_bounds__(256, 4)
main_kernel(const float* __restrict__ x, float* __restrict__ out) {
    __shared__ float x_shT[AA * XPITCH];    // 20640 B
    __shared__ float W_sh[CCH * 256];       //  8192 B
    __shared__ float g_sh[AA][CCH];

    const int bi   = blockIdx.x;
    const int b    = bi >> 1;
    const int half = bi & 1;
    const int tid  = threadIdx.x;
    const int s    = tid & 31;
    const int w    = tid >> 5;
    const int gq   = w >> 1;                // a-group 0..3 (rows 5gq..5gq+4)
    const int h    = w & 1;                 // c-half 0..1 (cols 4h..4h+3)

    // Stage W chunk [8][256].
    {
        const float4* Wg = reinterpret_cast<const float4*>(g_W);
        #pragma unroll
        for (int it = 0; it < 2; ++it) {
            const int i = tid + it * 256;    // < 512
            const int c = i >> 6, p4 = i & 63;
            reinterpret_cast<float4*>(W_sh)[c * 64 + p4] =
                Wg[c * 128 + half * 64 + p4];
        }
    }

    // Stage x half-chunk: coalesced float4 global loads, transposed scatter.
    // Store banks: word addr = 258*a + p == (2a + p) mod 32 -> <=2-way.
    {
        const float4* xg = reinterpret_cast<const float4*>(x)
                         + (size_t)b * 2560 + half * 1280;
        #pragma unroll
        for (int it = 0; it < 5; ++it) {
            const int i = tid + it * 256;    // < 1280
            const float4 v = xg[i];
            const int p  = i / 5;
            const int a0 = (i - p * 5) * 4;
            x_shT[(a0 + 0) * XPITCH + p] = v.x;
            x_shT[(a0 + 1) * XPITCH + p] = v.y;
            x_shT[(a0 + 2) * XPITCH + p] = v.z;
            x_shT[(a0 + 3) * XPITCH + p] = v.w;
        }
    }
    __syncthreads();

    // Packed accumulators: lo = even-p partial, hi = odd-p partial.
    unsigned long long acc2[5][4];
    #pragma unroll
    for (int m = 0; m < 5; ++m)
        #pragma unroll
        for (int n = 0; n < 4; ++n) acc2[m][n] = 0ULL;

    // Lane s covers position pairs {64j+2s, 64j+2s+1}, j = 0..3.
    // All offsets even -> 8B-aligned LDS.64; consecutive lanes -> consecutive
    // word pairs -> conflict-free on both x and W.
    #pragma unroll
    for (int j = 0; j < 4; ++j) {
        const int off = 64 * j + 2 * s;
        unsigned long long w2[4];
        #pragma unroll
        for (int n = 0; n < 4; ++n)
            w2[n] = *reinterpret_cast<const unsigned long long*>(
                &W_sh[(h * 4 + n) * 256 + off]);
        #pragma unroll
        for (int m = 0; m < 5; ++m) {
            const unsigned long long x2 =
                *reinterpret_cast<const unsigned long long*>(
                    &x_shT[(gq * 5 + m) * XPITCH + off]);
            #pragma unroll
            for (int n = 0; n < 4; ++n)
                FFMA2(acc2[m][n], x2, w2[n]);
        }
    }

    // Fold even/odd halves -> scalar acc[5][4].
    float acc[5][4];
    #pragma unroll
    for (int m = 0; m < 5; ++m)
        #pragma unroll
        for (int n = 0; n < 4; ++n) {
            float lo, hi;
            UNPACK2(lo, hi, acc2[m][n]);
            acc[m][n] = lo + hi;
        }

    // Value-combining butterfly reduce over lanes.
    const bool hi16 = (s & 16) != 0;
    const bool hi8  = (s & 8) != 0;
    float r1[5][2];
    #pragma unroll
    for (int m = 0; m < 5; ++m) {
        #pragma unroll
        for (int u = 0; u < 2; ++u) {
            const float a  = acc[m][2 * u];
            const float bb = acc[m][2 * u + 1];
            const float keep = hi16 ? bb : a;
            const float send = hi16 ? a : bb;
            r1[m][u] = keep + __shfl_xor_sync(0xffffffffu, send, 16);
        }
    }
    float r2[5];
    #pragma unroll
    for (int m = 0; m < 5; ++m) {
        const float a  = r1[m][0];
        const float bb = r1[m][1];
        const float keep = hi8 ? bb : a;
        const float send = hi8 ? a : bb;
        r2[m] = keep + __shfl_xor_sync(0xffffffffu, send, 8);
    }
    #pragma unroll
    for (int m = 0; m < 5; ++m) {
        r2[m] += __shfl_xor_sync(0xffffffffu, r2[m], 4);
        r2[m] += __shfl_xor_sync(0xffffffffu, r2[m], 2);
        r2[m] += __shfl_xor_sync(0xffffffffu, r2[m], 1);
    }
    if ((s & 7) == 0) {
        const int n = 2 * ((s >> 3) & 1) + ((s >> 4) & 1);
        #pragma unroll
        for (int m = 0; m < 5; ++m)
            g_sh[gq * 5 + m][h * 4 + n] = r2[m];
    }
    __syncthreads();

    // out[b,i,c] += sum_a U[a][i] * g[a][c]   (2 halves combine via atomics)
    if (tid < AA * CCH) {
        const int i = tid >> 3;
        const int c = tid & 7;
        float r = 0.f;
        #pragma unroll
        for (int a = 0; a < AA; ++a)
            r += __ldg(&g_U[a * AA + i]) * g_sh[a][c];
        atomicAdd(&out[(size_t)b * (AA * CCH) + tid], r);
    }
}

// ---------------------------------------------------------------------------
extern "C" void kernel_launch(void* const* d_in, const int* in_sizes, int n_in,
                              void* d_out, int out_size) {
    const float* x       = (const float*)d_in[0];
    const float* lpm     = (const float*)d_in[2];
    const float* pm      = (const float*)d_in[3];
    const float* w_first = (const float*)d_in[4];
    const float* w_rest  = (const float*)d_in[5];
    float* out = (float*)d_out;

    precompute_kernel<<<CCH + 1 + 160, 256>>>(lpm, pm, w_first, w_rest, out);
    main_kernel<<<BSEQ * 2, 256>>>(x, out);
}